// round 1
// baseline (speedup 1.0000x reference)
#include <cuda_runtime.h>
#include <cuda_bf16.h>
#include <math_constants.h>

// Problem constants (fixed by the dataset)
constexpr int NN = 100000;   // nodes
constexpr int EE = 1600000;  // edges
constexpr int DD = 128;      // model dim
constexpr int HH = 8;        // heads
// DH = 16, M = 3

// ---------------- scratch (static device globals; no allocation) -------------
__device__ float g_Q[NN * DD];
__device__ float g_K[NN * DD];
__device__ float g_V[NN * DD];
__device__ int   g_deg[NN];
__device__ int   g_rowptr[NN + 1];
__device__ int   g_cursor[NN];
__device__ int   g_eid[EE];
__device__ int   g_csrc[EE];
__device__ float g_max[NN * HH];
__device__ float g_sum[NN * HH];

// ---------------- QKV GEMM: C = x @ W + b for Wq, Wk, Wv ---------------------
// Tile: 128 rows x 128 cols (full D), K-chunks of 32. 256 threads, 8x8 microtile.
constexpr int XS_STRIDE = 132;  // padded to kill a-load bank conflicts
constexpr int GEMM_SMEM = (128 * XS_STRIDE + 32 * 128) * 4;

__global__ __launch_bounds__(256) void qkv_gemm(
    const float* __restrict__ x,
    const float* __restrict__ Wq, const float* __restrict__ bq,
    const float* __restrict__ Wk, const float* __restrict__ bk,
    const float* __restrict__ Wv, const float* __restrict__ bv,
    int n)
{
    extern __shared__ float smem[];
    float* xs = smem;                       // [128][XS_STRIDE]
    float* ws = smem + 128 * XS_STRIDE;     // [32][128]

    const int tid = threadIdx.x;
    const int tx = tid & 15;   // column group: cols {tx*4..+3, 64+tx*4..+3}
    const int ty = tid >> 4;   // row group:    rows {ty*4..+3, 64+ty*4..+3}
    const int row0 = blockIdx.x * 128;

    // Load x tile [128][128] as float4; OOB rows -> 0
    for (int i = tid; i < 128 * 32; i += 256) {
        int r = i >> 5, c = (i & 31) << 2;
        float4 v = make_float4(0.f, 0.f, 0.f, 0.f);
        if (row0 + r < n) v = *(const float4*)(x + (size_t)(row0 + r) * DD + c);
        *(float4*)(&xs[r * XS_STRIDE + c]) = v;
    }

    const float* Ws[3] = {Wq, Wk, Wv};
    const float* Bs[3] = {bq, bk, bv};
    float*       Os[3] = {g_Q, g_K, g_V};

    for (int w = 0; w < 3; ++w) {
        float acc[8][8];
#pragma unroll
        for (int i = 0; i < 8; ++i)
#pragma unroll
            for (int j = 0; j < 8; ++j) acc[i][j] = 0.f;

        const float* W = Ws[w];
        for (int kb = 0; kb < 4; ++kb) {
            __syncthreads();
            // load W chunk [32][128]
            for (int i = tid; i < 32 * 32; i += 256) {
                int r = i >> 5, c = (i & 31) << 2;
                *(float4*)(&ws[r * 128 + c]) =
                    *(const float4*)(W + (size_t)(kb * 32 + r) * DD + c);
            }
            __syncthreads();
#pragma unroll
            for (int kk = 0; kk < 32; ++kk) {
                float a[8], b[8];
#pragma unroll
                for (int i = 0; i < 4; ++i) {
                    a[i]     = xs[(ty * 4 + i) * XS_STRIDE + kb * 32 + kk];
                    a[4 + i] = xs[(64 + ty * 4 + i) * XS_STRIDE + kb * 32 + kk];
                }
                float4 b0 = *(float4*)(&ws[kk * 128 + tx * 4]);
                float4 b1 = *(float4*)(&ws[kk * 128 + 64 + tx * 4]);
                b[0] = b0.x; b[1] = b0.y; b[2] = b0.z; b[3] = b0.w;
                b[4] = b1.x; b[5] = b1.y; b[6] = b1.z; b[7] = b1.w;
#pragma unroll
                for (int i = 0; i < 8; ++i)
#pragma unroll
                    for (int j = 0; j < 8; ++j) acc[i][j] += a[i] * b[j];
            }
        }

        float4 bb0 = *(const float4*)(Bs[w] + tx * 4);
        float4 bb1 = *(const float4*)(Bs[w] + 64 + tx * 4);
        float* O = Os[w];
#pragma unroll
        for (int i = 0; i < 8; ++i) {
            int r = row0 + ((i < 4) ? (ty * 4 + i) : (64 + ty * 4 + (i - 4)));
            if (r < n) {
                float4 o0 = make_float4(acc[i][0] + bb0.x, acc[i][1] + bb0.y,
                                        acc[i][2] + bb0.z, acc[i][3] + bb0.w);
                float4 o1 = make_float4(acc[i][4] + bb1.x, acc[i][5] + bb1.y,
                                        acc[i][6] + bb1.z, acc[i][7] + bb1.w);
                *(float4*)(O + (size_t)r * DD + tx * 4) = o0;
                *(float4*)(O + (size_t)r * DD + 64 + tx * 4) = o1;
            }
        }
    }
}

// ---------------- CSR construction -------------------------------------------
__global__ void zero_deg(int n) {
    int i = blockIdx.x * blockDim.x + threadIdx.x;
    if (i < n) g_deg[i] = 0;
}

__global__ void hist_kernel(const int* __restrict__ dst, int E) {
    int i = blockIdx.x * blockDim.x + threadIdx.x;
    if (i < E) atomicAdd(&g_deg[dst[i]], 1);
}

// Single-block exclusive scan over g_deg -> g_rowptr, g_cursor
__global__ __launch_bounds__(1024) void scan_kernel(int n, int E) {
    __shared__ int partial[1024];
    const int t = threadIdx.x;
    const int chunk = (n + 1023) / 1024;
    const int beg = t * chunk;
    const int end = min(beg + chunk, n);

    int s = 0;
    for (int i = beg; i < end; ++i) s += g_deg[i];
    partial[t] = s;
    __syncthreads();
    for (int off = 1; off < 1024; off <<= 1) {
        int v = (t >= off) ? partial[t - off] : 0;
        __syncthreads();
        partial[t] += v;
        __syncthreads();
    }
    int run = (t == 0) ? 0 : partial[t - 1];
    for (int i = beg; i < end; ++i) {
        g_rowptr[i] = run;
        g_cursor[i] = run;
        run += g_deg[i];
    }
    if (t == 0) g_rowptr[n] = E;
}

__global__ void scatter_kernel(const int* __restrict__ src,
                               const int* __restrict__ dst, int E) {
    int i = blockIdx.x * blockDim.x + threadIdx.x;
    if (i < E) {
        int p = atomicAdd(&g_cursor[dst[i]], 1);
        g_eid[p] = i;
        g_csrc[p] = src[i];
    }
}

// ---------------- per-node online-softmax attention --------------------------
// One warp per node. lane -> (head = lane/4, dim-quad = lane%4).
__global__ __launch_bounds__(256) void node_attn(
    const float* __restrict__ pi, const float* __restrict__ view_w,
    float* __restrict__ ns_out, float* __restrict__ attn_out, int n)
{
    int warp = (blockIdx.x * blockDim.x + threadIdx.x) >> 5;
    if (warp >= n) return;
    const int lane = threadIdx.x & 31;
    const int h = lane >> 2;
    const int dsub = lane & 3;
    const int nd = warp;

    const float4* Q4 = (const float4*)g_Q;
    const float4* K4 = (const float4*)g_K;
    const float4* V4 = (const float4*)g_V;

    const float4 qv = Q4[nd * 32 + h * 4 + dsub];
    const float p0 = pi[nd * 24 + h * 3 + 0];
    const float p1 = pi[nd * 24 + h * 3 + 1];
    const float p2 = pi[nd * 24 + h * 3 + 2];

    const int beg = g_rowptr[nd];
    const int end = g_rowptr[nd + 1];

    float m_run = -CUDART_INF_F;
    float s_run = 0.f;
    float ax = 0.f, ay = 0.f, az = 0.f, aw = 0.f;

    for (int j = beg; j < end; ++j) {
        const int eid = g_eid[j];
        const int sN = g_csrc[j];
        float4 kv = K4[sN * 32 + h * 4 + dsub];
        float d = qv.x * kv.x + qv.y * kv.y + qv.z * kv.z + qv.w * kv.w;
        d += __shfl_xor_sync(0xffffffff, d, 1);
        d += __shfl_xor_sync(0xffffffff, d, 2);   // all 4 lanes of quad: full 16-dim dot

        float vw0 = view_w[eid * 3 + 0];
        float vw1 = view_w[eid * 3 + 1];
        float vw2 = view_w[eid * 3 + 2];
        float mix = p0 * vw0 + p1 * vw1 + p2 * vw2;

        float sc = d * 0.25f + __logf(fmaxf(mix, 1e-8f));
        if (!(mix > 0.f)) sc = -1e9f;
        if (dsub == 0) attn_out[(size_t)eid * HH + h] = sc;  // score stored; finalized later

        float nm = fmaxf(m_run, sc);
        float scale = __expf(m_run - nm);   // first iter: exp(-inf)=0
        float p = (sc > -1e8f) ? __expf(sc - nm) : 0.f;
        float4 vv = V4[sN * 32 + h * 4 + dsub];
        s_run = s_run * scale + p;
        ax = ax * scale + p * vv.x;
        ay = ay * scale + p * vv.y;
        az = az * scale + p * vv.z;
        aw = aw * scale + p * vv.w;
        m_run = nm;
    }

    float inv = 1.f / fmaxf(s_run, 1e-8f);
    float4 o = make_float4(ax * inv, ay * inv, az * inv, aw * inv);
    ((float4*)ns_out)[nd * 32 + h * 4 + dsub] = o;
    if (dsub == 0) {
        g_max[nd * HH + h] = m_run;
        g_sum[nd * HH + h] = s_run;
    }
}

// ---------------- finalize attn: score -> normalized weight ------------------
__global__ void finalize_attn(const int* __restrict__ dst,
                              float* __restrict__ attn_out, int E) {
    int i = blockIdx.x * blockDim.x + threadIdx.x;
    if (i >= E * HH) return;
    int e = i >> 3, h = i & 7;
    float sc = attn_out[i];
    float a = 0.f;
    if (sc > -1e8f) {
        int d = dst[e];
        a = __expf(sc - g_max[d * HH + h]) / fmaxf(g_sum[d * HH + h], 1e-8f);
    }
    attn_out[i] = a;
}

// ---------------- launch ------------------------------------------------------
extern "C" void kernel_launch(void* const* d_in, const int* in_sizes, int n_in,
                              void* d_out, int out_size) {
    const float* x   = (const float*)d_in[0];
    const float* pi  = (const float*)d_in[1];
    const float* vw  = (const float*)d_in[2];
    const float* Wq  = (const float*)d_in[3];
    const float* bq  = (const float*)d_in[4];
    const float* Wk  = (const float*)d_in[5];
    const float* bk  = (const float*)d_in[6];
    const float* Wv  = (const float*)d_in[7];
    const float* bv  = (const float*)d_in[8];
    const int*   src = (const int*)d_in[9];
    const int*   dst = (const int*)d_in[10];

    const int n = in_sizes[0] / DD;   // 100000
    const int E = in_sizes[9];        // 1600000

    float* out = (float*)d_out;
    float* ns_out = out;                          // [n, H, DH]
    float* attn_out = out + (size_t)n * DD;       // [E, H]

    cudaFuncSetAttribute(qkv_gemm, cudaFuncAttributeMaxDynamicSharedMemorySize,
                         GEMM_SMEM);

    // 1) QKV projections
    qkv_gemm<<<(n + 127) / 128, 256, GEMM_SMEM>>>(x, Wq, bq, Wk, bk, Wv, bv, n);

    // 2) CSR by dst
    zero_deg<<<(n + 255) / 256, 256>>>(n);
    hist_kernel<<<(E + 255) / 256, 256>>>(dst, E);
    scan_kernel<<<1, 1024>>>(n, E);
    scatter_kernel<<<(E + 255) / 256, 256>>>(src, dst, E);

    // 3) one warp per node: scores + online softmax + weighted V aggregation
    node_attn<<<(n + 7) / 8, 256>>>(pi, vw, ns_out, attn_out, n);

    // 4) finalize per-edge attention weights
    finalize_attn<<<(E * HH + 255) / 256, 256>>>(dst, attn_out, E);
}

// round 3
// speedup vs baseline: 1.2657x; 1.2657x over previous
#include <cuda_runtime.h>
#include <cuda_bf16.h>
#include <math_constants.h>

// Problem constants (fixed by the dataset)
constexpr int NN = 100000;   // nodes
constexpr int EE = 1600000;  // edges
constexpr int DD = 128;      // model dim
constexpr int HH = 8;        // heads
// DH = 16, M = 3

// ---------------- scratch (static device globals; no allocation) -------------
__device__ float g_Q[NN * DD];
__device__ float g_K[NN * DD];
__device__ float g_V[NN * DD];
__device__ int   g_deg[NN];
__device__ int   g_rowptr[NN + 1];
__device__ int   g_cursor[NN];
__device__ int2  g_edge[EE];          // (eid, src) packed
__device__ float g_max[NN * HH];
__device__ float g_sum[NN * HH];
__device__ int   g_bsum[128];
__device__ int   g_boff[128];

// ---------------- f32x2 packed helpers (sm_100+) ------------------------------
typedef unsigned long long ull;

__device__ __forceinline__ void fma2(ull& d, ull a, ull b) {
    asm("fma.rn.f32x2 %0, %1, %2, %0;" : "+l"(d) : "l"(a), "l"(b));
}
__device__ __forceinline__ float2 upk(ull v) {
    float2 r; asm("mov.b64 {%0,%1}, %2;" : "=f"(r.x), "=f"(r.y) : "l"(v)); return r;
}
__device__ __forceinline__ ull swp(ull v) {
    ull r;
    asm("{\n\t.reg .b32 a,b;\n\tmov.b64 {a,b}, %1;\n\tmov.b64 %0, {b,a};\n\t}"
        : "=l"(r) : "l"(v));
    return r;
}

// ---------------- QKV GEMM: C = x @ W + b for Wq, Wk, Wv ----------------------
// 128x128 tile, K-chunks of 32, 256 threads, 8x8 microtile done as f32x2 pairs.
// A tile stored TRANSPOSED in smem (xs_t[k][row]) so row-pairs load as packed b64.
constexpr int XT = 130;  // transposed-A row stride
constexpr int GEMM_SMEM = (128 * XT + 32 * 128) * 4;

__global__ __launch_bounds__(256) void qkv_gemm(
    const float* __restrict__ x,
    const float* __restrict__ Wq, const float* __restrict__ bq,
    const float* __restrict__ Wk, const float* __restrict__ bk,
    const float* __restrict__ Wv, const float* __restrict__ bv,
    int n)
{
    extern __shared__ float smem[];
    float* xs_t = smem;                   // [128 k][XT rows]
    float* ws   = smem + 128 * XT;        // [32 k][128 cols]

    const int tid = threadIdx.x;
    const int tx = tid & 15;   // cols {tx*4..+3, 64+tx*4..+3}
    const int ty = tid >> 4;   // rows {ty*4..+3, 64+ty*4..+3}
    const int row0 = blockIdx.x * 128;

    // Load x tile [128 rows][128 k], store transposed: xs_t[k][row]
    for (int i = tid; i < 128 * 32; i += 256) {
        int r = i >> 5, c = (i & 31) << 2;
        float4 v = make_float4(0.f, 0.f, 0.f, 0.f);
        if (row0 + r < n) v = *(const float4*)(x + (size_t)(row0 + r) * DD + c);
        xs_t[(c + 0) * XT + r] = v.x;
        xs_t[(c + 1) * XT + r] = v.y;
        xs_t[(c + 2) * XT + r] = v.z;
        xs_t[(c + 3) * XT + r] = v.w;
    }

    const float* Ws[3] = {Wq, Wk, Wv};
    const float* Bs[3] = {bq, bk, bv};
    float*       Os[3] = {g_Q, g_K, g_V};

    const int ra = ty * 4;        // row base (lower half); +64 for upper
    const int ca = tx * 4;        // col base (lower half); +64 for upper

    for (int w = 0; w < 3; ++w) {
        ull accD[4][4], accX[4][4];
#pragma unroll
        for (int i = 0; i < 4; ++i)
#pragma unroll
            for (int j = 0; j < 4; ++j) { accD[i][j] = 0ull; accX[i][j] = 0ull; }

        const float* W = Ws[w];
        for (int kb = 0; kb < 4; ++kb) {
            __syncthreads();
            for (int i = tid; i < 32 * 32; i += 256) {
                int r = i >> 5, c = (i & 31) << 2;
                *(float4*)(&ws[r * 128 + c]) =
                    *(const float4*)(W + (size_t)(kb * 32 + r) * DD + c);
            }
            __syncthreads();
#pragma unroll
            for (int kk = 0; kk < 32; ++kk) {
                // FIX vs R2: index A by GLOBAL k = kb*32 + kk (this was the bug)
                const float* arow = xs_t + (kb * 32 + kk) * XT;
                ull aP[4];
                aP[0] = *(const ull*)(arow + ra);          // (r0,r1)
                aP[1] = *(const ull*)(arow + ra + 2);      // (r2,r3)
                aP[2] = *(const ull*)(arow + 64 + ra);     // (r4,r5)
                aP[3] = *(const ull*)(arow + 64 + ra + 2); // (r6,r7)

                const float* brow = ws + kk * 128;
                ulonglong2 bl = *(const ulonglong2*)(brow + ca);
                ulonglong2 bh = *(const ulonglong2*)(brow + 64 + ca);
                ull bP[4] = {bl.x, bl.y, bh.x, bh.y};
                ull bS[4] = {swp(bl.x), swp(bl.y), swp(bh.x), swp(bh.y)};

#pragma unroll
                for (int i = 0; i < 4; ++i)
#pragma unroll
                    for (int j = 0; j < 4; ++j) {
                        fma2(accD[i][j], aP[i], bP[j]);  // (r_lo*c_lo, r_hi*c_hi)
                        fma2(accX[i][j], aP[i], bS[j]);  // (r_lo*c_hi, r_hi*c_lo)
                    }
            }
        }

        // unpack diagonal pairs into vals[8][8]
        float vals[8][8];
#pragma unroll
        for (int i2 = 0; i2 < 4; ++i2)
#pragma unroll
            for (int j2 = 0; j2 < 4; ++j2) {
                float2 d = upk(accD[i2][j2]);
                float2 s = upk(accX[i2][j2]);
                vals[2 * i2][2 * j2]         = d.x;
                vals[2 * i2 + 1][2 * j2 + 1] = d.y;
                vals[2 * i2][2 * j2 + 1]     = s.x;
                vals[2 * i2 + 1][2 * j2]     = s.y;
            }

        float4 bb0 = *(const float4*)(Bs[w] + ca);
        float4 bb1 = *(const float4*)(Bs[w] + 64 + ca);
        float* O = Os[w];
#pragma unroll
        for (int i = 0; i < 8; ++i) {
            int r = row0 + ((i < 4) ? (ra + i) : (64 + ra + (i - 4)));
            if (r < n) {
                float4 o0 = make_float4(vals[i][0] + bb0.x, vals[i][1] + bb0.y,
                                        vals[i][2] + bb0.z, vals[i][3] + bb0.w);
                float4 o1 = make_float4(vals[i][4] + bb1.x, vals[i][5] + bb1.y,
                                        vals[i][6] + bb1.z, vals[i][7] + bb1.w);
                *(float4*)(O + (size_t)r * DD + ca) = o0;
                *(float4*)(O + (size_t)r * DD + 64 + ca) = o1;
            }
        }
    }
}

// ---------------- CSR construction -------------------------------------------
__global__ void zero_deg(int n) {
    int i = blockIdx.x * blockDim.x + threadIdx.x;
    if (i < n) g_deg[i] = 0;
}

__global__ void hist_kernel(const int* __restrict__ dst, int E) {
    int i = blockIdx.x * blockDim.x + threadIdx.x;
    if (i < E) atomicAdd(&g_deg[dst[i]], 1);
}

// 3-phase multi-block exclusive scan: deg -> rowptr/cursor
__global__ __launch_bounds__(1024) void scan1(int n) {
    __shared__ int sm[1024];
    const int t = threadIdx.x;
    const int i = blockIdx.x * 1024 + t;
    int v = (i < n) ? g_deg[i] : 0;
    sm[t] = v;
    __syncthreads();
    for (int off = 1; off < 1024; off <<= 1) {
        int u = (t >= off) ? sm[t - off] : 0;
        __syncthreads();
        sm[t] += u;
        __syncthreads();
    }
    if (i < n) g_rowptr[i] = sm[t] - v;  // local exclusive
    if (t == 1023) g_bsum[blockIdx.x] = sm[t];
}

__global__ __launch_bounds__(128) void scan2(int nb) {
    __shared__ int sm[128];
    const int t = threadIdx.x;
    int v = (t < nb) ? g_bsum[t] : 0;
    sm[t] = v;
    __syncthreads();
    for (int off = 1; off < 128; off <<= 1) {
        int u = (t >= off) ? sm[t - off] : 0;
        __syncthreads();
        sm[t] += u;
        __syncthreads();
    }
    if (t < nb) g_boff[t] = sm[t] - v;  // exclusive
}

__global__ __launch_bounds__(1024) void scan3(int n, int E) {
    const int i = blockIdx.x * 1024 + threadIdx.x;
    if (i < n) {
        int r = g_rowptr[i] + g_boff[i >> 10];
        g_rowptr[i] = r;
        g_cursor[i] = r;
    }
    if (i == 0) g_rowptr[n] = E;
}

__global__ void scatter_kernel(const int* __restrict__ src,
                               const int* __restrict__ dst, int E) {
    int i = blockIdx.x * blockDim.x + threadIdx.x;
    if (i < E) {
        int p = atomicAdd(&g_cursor[dst[i]], 1);
        g_edge[p] = make_int2(i, src[i]);
    }
}

// ---------------- per-node online-softmax attention --------------------------
// One warp per node. lane -> (head = lane/4, dim-quad = lane%4).
__global__ __launch_bounds__(256) void node_attn(
    const float* __restrict__ pi, const float* __restrict__ view_w,
    float* __restrict__ ns_out, float* __restrict__ attn_out, int n)
{
    int warp = (blockIdx.x * blockDim.x + threadIdx.x) >> 5;
    if (warp >= n) return;
    const int lane = threadIdx.x & 31;
    const int h = lane >> 2;
    const int dsub = lane & 3;
    const int nd = warp;

    const float4* Q4 = (const float4*)g_Q;
    const float4* K4 = (const float4*)g_K;
    const float4* V4 = (const float4*)g_V;

    const float4 qv = Q4[nd * 32 + h * 4 + dsub];
    const float p0 = pi[nd * 24 + h * 3 + 0];
    const float p1 = pi[nd * 24 + h * 3 + 1];
    const float p2 = pi[nd * 24 + h * 3 + 2];

    const int beg = g_rowptr[nd];
    const int end = g_rowptr[nd + 1];

    float m_run = -CUDART_INF_F;
    float s_run = 0.f;
    float ax = 0.f, ay = 0.f, az = 0.f, aw = 0.f;

    for (int j = beg; j < end; ++j) {
        const int2 e = g_edge[j];
        const int eid = e.x;
        const int sN = e.y;
        float4 kv = K4[sN * 32 + h * 4 + dsub];
        float d = qv.x * kv.x + qv.y * kv.y + qv.z * kv.z + qv.w * kv.w;
        d += __shfl_xor_sync(0xffffffff, d, 1);
        d += __shfl_xor_sync(0xffffffff, d, 2);   // full 16-dim dot in each quad

        float vw0 = view_w[eid * 3 + 0];
        float vw1 = view_w[eid * 3 + 1];
        float vw2 = view_w[eid * 3 + 2];
        float mix = p0 * vw0 + p1 * vw1 + p2 * vw2;

        float sc = d * 0.25f + __logf(fmaxf(mix, 1e-8f));
        if (!(mix > 0.f)) sc = -1e9f;
        if (dsub == 0) attn_out[(size_t)eid * HH + h] = sc;  // raw score; finalized later

        float nm = fmaxf(m_run, sc);
        float scale = __expf(m_run - nm);
        float p = (sc > -1e8f) ? __expf(sc - nm) : 0.f;
        float4 vv = V4[sN * 32 + h * 4 + dsub];
        s_run = s_run * scale + p;
        ax = ax * scale + p * vv.x;
        ay = ay * scale + p * vv.y;
        az = az * scale + p * vv.z;
        aw = aw * scale + p * vv.w;
        m_run = nm;
    }

    float inv = 1.f / fmaxf(s_run, 1e-8f);
    float4 o = make_float4(ax * inv, ay * inv, az * inv, aw * inv);
    ((float4*)ns_out)[nd * 32 + h * 4 + dsub] = o;
    if (dsub == 0) {
        g_max[nd * HH + h] = m_run;
        g_sum[nd * HH + h] = s_run;
    }
}

// ---------------- finalize attn: score -> normalized weight ------------------
__global__ void finalize_attn(const int* __restrict__ dst,
                              float* __restrict__ attn_out, int E) {
    int i = blockIdx.x * blockDim.x + threadIdx.x;
    if (i >= E * HH) return;
    int e = i >> 3, h = i & 7;
    float sc = attn_out[i];
    float a = 0.f;
    if (sc > -1e8f) {
        int d = dst[e];
        a = __expf(sc - g_max[d * HH + h]) / fmaxf(g_sum[d * HH + h], 1e-8f);
    }
    attn_out[i] = a;
}

// ---------------- launch ------------------------------------------------------
extern "C" void kernel_launch(void* const* d_in, const int* in_sizes, int n_in,
                              void* d_out, int out_size) {
    const float* x   = (const float*)d_in[0];
    const float* pi  = (const float*)d_in[1];
    const float* vw  = (const float*)d_in[2];
    const float* Wq  = (const float*)d_in[3];
    const float* bq  = (const float*)d_in[4];
    const float* Wk  = (const float*)d_in[5];
    const float* bk  = (const float*)d_in[6];
    const float* Wv  = (const float*)d_in[7];
    const float* bv  = (const float*)d_in[8];
    const int*   src = (const int*)d_in[9];
    const int*   dst = (const int*)d_in[10];

    const int n = in_sizes[0] / DD;   // 100000
    const int E = in_sizes[9];        // 1600000

    float* out = (float*)d_out;
    float* ns_out = out;                          // [n, H, DH]
    float* attn_out = out + (size_t)n * DD;       // [E, H]

    cudaFuncSetAttribute(qkv_gemm, cudaFuncAttributeMaxDynamicSharedMemorySize,
                         GEMM_SMEM);

    // 1) QKV projections (f32x2 packed FMA)
    qkv_gemm<<<(n + 127) / 128, 256, GEMM_SMEM>>>(x, Wq, bq, Wk, bk, Wv, bv, n);

    // 2) CSR by dst (multi-block scan)
    const int nb = (n + 1023) / 1024;
    zero_deg<<<(n + 255) / 256, 256>>>(n);
    hist_kernel<<<(E + 255) / 256, 256>>>(dst, E);
    scan1<<<nb, 1024>>>(n);
    scan2<<<1, 128>>>(nb);
    scan3<<<nb, 1024>>>(n, E);
    scatter_kernel<<<(E + 255) / 256, 256>>>(src, dst, E);

    // 3) one warp per node: scores + online softmax + weighted V aggregation
    node_attn<<<(n + 7) / 8, 256>>>(pi, vw, ns_out, attn_out, n);

    // 4) finalize per-edge attention weights
    finalize_attn<<<(E * HH + 255) / 256, 256>>>(dst, attn_out, E);
}